// round 12
// baseline (speedup 1.0000x reference)
#include <cuda_runtime.h>
#include <cuda_bf16.h>
#include <cstdint>

#define B_ 2
#define S_ 2048
#define D_ 2048
#define H_ 16
#define HD_ 128
#define WINDOW_ 256
#define MTOT_ (B_ * S_)     // 4096
#define KDIM_ D_            // 2048

// -------- scratch (static __device__ arrays; no runtime allocation) --------
__device__ __align__(1024) __nv_bfloat16 g_Xhi [(size_t)MTOT_ * D_];
__device__ __align__(1024) __nv_bfloat16 g_Xlo [(size_t)MTOT_ * D_];
__device__ __align__(1024) __nv_bfloat16 g_Qhi [(size_t)MTOT_ * D_];
__device__ __align__(1024) __nv_bfloat16 g_Qlo [(size_t)MTOT_ * D_];
__device__ __align__(1024) __nv_bfloat16 g_Khi [(size_t)MTOT_ * D_];
__device__ __align__(1024) __nv_bfloat16 g_Klo [(size_t)MTOT_ * D_];
__device__ __align__(1024) __nv_bfloat16 g_Vhi [(size_t)MTOT_ * D_];
__device__ __align__(1024) __nv_bfloat16 g_Vlo [(size_t)MTOT_ * D_];
__device__ __align__(1024) __nv_bfloat16 g_AOhi[(size_t)MTOT_ * D_];
__device__ __align__(1024) __nv_bfloat16 g_AOlo[(size_t)MTOT_ * D_];
__device__ __align__(1024) __nv_bfloat16 g_Wqt_hi[(size_t)D_ * D_];
__device__ __align__(1024) __nv_bfloat16 g_Wqt_lo[(size_t)D_ * D_];
__device__ __align__(1024) __nv_bfloat16 g_Wkt_hi[(size_t)D_ * D_];
__device__ __align__(1024) __nv_bfloat16 g_Wkt_lo[(size_t)D_ * D_];
__device__ __align__(1024) __nv_bfloat16 g_Wvt_hi[(size_t)D_ * D_];
__device__ __align__(1024) __nv_bfloat16 g_Wvt_lo[(size_t)D_ * D_];
__device__ __align__(1024) __nv_bfloat16 g_Wot_hi[(size_t)D_ * D_];
__device__ __align__(1024) __nv_bfloat16 g_Wot_lo[(size_t)D_ * D_];

// ============================================================================
// helpers (generic PTX only — sm_80-compatible, safe for compute_103)
// ============================================================================
__device__ __forceinline__ uint32_t smem_u32(const void* p) {
    uint32_t a;
    asm("{ .reg .u64 t; cvta.to.shared.u64 t, %1; cvt.u32.u64 %0, t; }"
        : "=r"(a) : "l"(p));
    return a;
}

#define SWZ(o) ((o) ^ (((o) >> 3) & 0x70))
// packed rows: two 64B logical rows per 128B swizzled line
#define PKOFF(row, b) SWZ((((row) >> 1) << 7) + (((row) & 1) << 6) + (b))

#define CP_ASYNC16(dst, src) \
    asm volatile("cp.async.cg.shared.global [%0], [%1], 16;" \
                 :: "r"(dst), "l"(src) : "memory")
#define CP_COMMIT() asm volatile("cp.async.commit_group;" ::: "memory")
#define CP_WAIT0()  asm volatile("cp.async.wait_group 0;" ::: "memory")
#define CP_WAIT1()  asm volatile("cp.async.wait_group 1;" ::: "memory")
#define CP_WAIT2()  asm volatile("cp.async.wait_group 2;" ::: "memory")

#define LDSM_X4(rr, addr) \
    asm volatile("ldmatrix.sync.aligned.m8n8.x4.shared.b16 {%0,%1,%2,%3}, [%4];" \
        : "=r"((rr)[0]), "=r"((rr)[1]), "=r"((rr)[2]), "=r"((rr)[3]) : "r"(addr))

#define LDSM_X4_T(rr, addr) \
    asm volatile("ldmatrix.sync.aligned.m8n8.x4.trans.shared.b16 {%0,%1,%2,%3}, [%4];" \
        : "=r"((rr)[0]), "=r"((rr)[1]), "=r"((rr)[2]), "=r"((rr)[3]) : "r"(addr))

#define MMA_BF16(cc, aa, b0, b1) \
    asm volatile("mma.sync.aligned.m16n8k16.row.col.f32.bf16.bf16.f32 " \
        "{%0,%1,%2,%3}, {%4,%5,%6,%7}, {%8,%9}, {%0,%1,%2,%3};" \
        : "+f"((cc)[0]), "+f"((cc)[1]), "+f"((cc)[2]), "+f"((cc)[3]) \
        : "r"((aa)[0]), "r"((aa)[1]), "r"((aa)[2]), "r"((aa)[3]), \
          "r"(b0), "r"(b1))

// pack two f32 into bf16x2: low half = lo, high half = hi
__device__ __forceinline__ uint32_t pack_bf16(float lo, float hi) {
    uint32_t r;
    asm("cvt.rn.bf16x2.f32 %0, %1, %2;" : "=r"(r) : "f"(hi), "f"(lo));
    return r;
}
__device__ __forceinline__ float2 unpack_bf16(uint32_t u) {
    __nv_bfloat162 b = *reinterpret_cast<__nv_bfloat162*>(&u);
    return make_float2(__bfloat162float(b.x), __bfloat162float(b.y));
}

// ============================================================================
// bf16 3-split GEMM via mma.sync: 256x128 CTA tile, 8 warps (64x64 each,
// 4m x 2n), BK=32 packed-row layout, 3-stage cp.async ring, 1 CTA/SM.
// D = Ah*Bh + Ah*Bl + Al*Bh (fp32 accum).
// Bigger M-tile cuts L2 read traffic per output by 25% vs 128x128.
// ============================================================================
#define TILE_A  16384      // 256x32 bf16 (packed 64B rows)
#define TILE_Bt 8192       // 128x32 bf16
#define STAGE_B (2 * TILE_A + 2 * TILE_Bt)   // 49152
#define NCHUNKS 64         // K / 32
#define GEMM_SMEM (3 * STAGE_B)   // 147456 -> 1 CTA/SM

struct G3 {
    const __nv_bfloat16 *Ah, *Al;
    const __nv_bfloat16 *Bh0, *Bl0, *Bh1, *Bl1, *Bh2, *Bl2;
    __nv_bfloat16 *Ch0, *Cl0, *Ch1, *Cl1, *Ch2, *Cl2;   // split outputs
    float* Cf;                                           // fp32 output
    const float* bias;
};

__device__ __forceinline__ void issue_chunk(
    const __nv_bfloat16* Ah, const __nv_bfloat16* Al,
    const __nv_bfloat16* Bh, const __nv_bfloat16* Bl,
    int t, int tid, int m0, int n0, uint32_t sb)
{
    const int k0 = t << 5;   // BK = 32
    const uint32_t stg = sb + (t % 3) * STAGE_B;
    // A tiles: 256 rows x 64B = 1024 16B-vectors each
#pragma unroll
    for (int v = 0; v < 4; v++) {
        const int slot = (v << 8) + tid;       // 0..1023
        const int row  = slot >> 2;            // 0..255
        const int c16  = slot & 3;
        const uint32_t off = PKOFF(row, c16 * 16);
        const size_t go = (size_t)(m0 + row) * KDIM_ + k0;
        CP_ASYNC16(stg + off,          (const char*)(Ah + go) + c16 * 16);
        CP_ASYNC16(stg + TILE_A + off, (const char*)(Al + go) + c16 * 16);
    }
    // B tiles: 128 rows x 64B = 512 vectors each
#pragma unroll
    for (int v = 0; v < 2; v++) {
        const int slot = (v << 8) + tid;       // 0..511
        const int row  = slot >> 2;            // 0..127
        const int c16  = slot & 3;
        const uint32_t off = PKOFF(row, c16 * 16);
        const size_t go = (size_t)(n0 + row) * KDIM_ + k0;
        CP_ASYNC16(stg + 2 * TILE_A + off,           (const char*)(Bh + go) + c16 * 16);
        CP_ASYNC16(stg + 2 * TILE_A + TILE_Bt + off, (const char*)(Bl + go) + c16 * 16);
    }
}

__global__ __launch_bounds__(256, 1)
void gemm_bf16x3(G3 ga)
{
    extern __shared__ __align__(1024) char smg[];
    const uint32_t sb = smem_u32(smg);
    const int tid = threadIdx.x;
    const int wid = tid >> 5, lid = tid & 31;
    const int warp_m = wid & 3;        // 0..3 (64 rows each)
    const int warp_n = wid >> 2;       // 0..1 (64 cols each)
    const int m0 = blockIdx.y << 8;    // 256-row tiles
    const int n0 = blockIdx.x << 7;    // 128-col tiles
    const int z  = blockIdx.z;

    const __nv_bfloat16* Bh = (z == 0) ? ga.Bh0 : (z == 1) ? ga.Bh1 : ga.Bh2;
    const __nv_bfloat16* Bl = (z == 0) ? ga.Bl0 : (z == 1) ? ga.Bl1 : ga.Bl2;

    const int grp = lid >> 3;
    const int lr  = lid & 7;

    float c[4][8][4];
#pragma unroll
    for (int mt = 0; mt < 4; mt++)
#pragma unroll
        for (int nt = 0; nt < 8; nt++)
#pragma unroll
            for (int q = 0; q < 4; q++) c[mt][nt][q] = 0.f;

    const int a_row = warp_m * 64 + (grp & 1) * 8 + lr;   // + mt*16 (0..255)
    const int a_kb  = (grp >> 1) * 16;                    // + kt*32
    const int b_row = warp_n * 64 + (grp >> 1) * 8 + lr;  // + nb*16 (0..127)
    const int b_kb  = (grp & 1) * 16;                     // + kt*32

    issue_chunk(ga.Ah, ga.Al, Bh, Bl, 0, tid, m0, n0, sb); CP_COMMIT();
    issue_chunk(ga.Ah, ga.Al, Bh, Bl, 1, tid, m0, n0, sb); CP_COMMIT();

    for (int t = 0; t < NCHUNKS; t++) {
        if (t + 2 < NCHUNKS) {
            issue_chunk(ga.Ah, ga.Al, Bh, Bl, t + 2, tid, m0, n0, sb);
            CP_COMMIT();
            CP_WAIT2();          // chunk t landed
        } else if (t + 1 < NCHUNKS) {
            CP_WAIT1();
        } else {
            CP_WAIT0();
        }
        __syncthreads();

        const uint32_t Ahs = sb + (t % 3) * STAGE_B;
        const uint32_t Als = Ahs + TILE_A;
        const uint32_t Bhs = Ahs + 2 * TILE_A;
        const uint32_t Bls = Bhs + TILE_Bt;

#pragma unroll
        for (int kt = 0; kt < 2; kt++) {
            uint32_t bh[4][4], bl[4][4];
#pragma unroll
            for (int nb = 0; nb < 4; nb++) {
                const uint32_t bo = PKOFF(b_row + nb * 16, kt * 32 + b_kb);
                LDSM_X4(bh[nb], Bhs + bo);
                LDSM_X4(bl[nb], Bls + bo);
            }
#pragma unroll
            for (int mt = 0; mt < 4; mt++) {
                uint32_t ah[4], al[4];
                const uint32_t ao = PKOFF(a_row + mt * 16, kt * 32 + a_kb);
                LDSM_X4(ah, Ahs + ao);
                LDSM_X4(al, Als + ao);
#pragma unroll
                for (int nb = 0; nb < 4; nb++) {
                    MMA_BF16(c[mt][2 * nb],     ah, bh[nb][0], bh[nb][1]);
                    MMA_BF16(c[mt][2 * nb + 1], ah, bh[nb][2], bh[nb][3]);
                    MMA_BF16(c[mt][2 * nb],     ah, bl[nb][0], bl[nb][1]);
                    MMA_BF16(c[mt][2 * nb + 1], ah, bl[nb][2], bl[nb][3]);
                    MMA_BF16(c[mt][2 * nb],     al, bh[nb][0], bh[nb][1]);
                    MMA_BF16(c[mt][2 * nb + 1], al, bh[nb][2], bh[nb][3]);
                }
            }
        }
        __syncthreads();
    }

    // ---- epilogue ----
    const int l4 = lid >> 2;
    const int l2 = (lid & 3) << 1;
    if (ga.Cf) {
        float* C = ga.Cf;
#pragma unroll
        for (int mt = 0; mt < 4; mt++) {
            const int row = m0 + warp_m * 64 + mt * 16 + l4;
#pragma unroll
            for (int nt = 0; nt < 8; nt++) {
                const int col = n0 + warp_n * 64 + nt * 8 + l2;
                float2 v0 = make_float2(c[mt][nt][0], c[mt][nt][1]);
                float2 v1 = make_float2(c[mt][nt][2], c[mt][nt][3]);
                const float b0 = ga.bias[col], b1 = ga.bias[col + 1];
                v0.x += b0; v0.y += b1;
                v1.x += b0; v1.y += b1;
                *(float2*)(C + (size_t)row * D_ + col)       = v0;
                *(float2*)(C + (size_t)(row + 8) * D_ + col) = v1;
            }
        }
    } else {
        __nv_bfloat16* Ch = (z == 0) ? ga.Ch0 : (z == 1) ? ga.Ch1 : ga.Ch2;
        __nv_bfloat16* Cl = (z == 0) ? ga.Cl0 : (z == 1) ? ga.Cl1 : ga.Cl2;
#pragma unroll
        for (int mt = 0; mt < 4; mt++) {
            const int row = m0 + warp_m * 64 + mt * 16 + l4;
#pragma unroll
            for (int nt = 0; nt < 8; nt++) {
                const int col = n0 + warp_n * 64 + nt * 8 + l2;
                const size_t o0 = (size_t)row * D_ + col;
                const size_t o1 = (size_t)(row + 8) * D_ + col;
                uint32_t h0 = pack_bf16(c[mt][nt][0], c[mt][nt][1]);
                uint32_t h1 = pack_bf16(c[mt][nt][2], c[mt][nt][3]);
                float2 f0 = unpack_bf16(h0), f1 = unpack_bf16(h1);
                uint32_t l0p = pack_bf16(c[mt][nt][0] - f0.x, c[mt][nt][1] - f0.y);
                uint32_t l1p = pack_bf16(c[mt][nt][2] - f1.x, c[mt][nt][3] - f1.y);
                *(uint32_t*)(Ch + o0) = h0;
                *(uint32_t*)(Ch + o1) = h1;
                *(uint32_t*)(Cl + o0) = l0p;
                *(uint32_t*)(Cl + o1) = l1p;
            }
        }
    }
}

// ============================================================================
// fp32 -> (hi, lo) bf16 split, elementwise (vectorized x4)
// ============================================================================
__global__ void split_f32x4(const float4* __restrict__ in,
                            __nv_bfloat162* __restrict__ hi,
                            __nv_bfloat162* __restrict__ lo, int n4)
{
    int i = blockIdx.x * blockDim.x + threadIdx.x;
    if (i >= n4) return;
    float4 x = in[i];
    __nv_bfloat16 h0 = __float2bfloat16(x.x);
    __nv_bfloat16 h1 = __float2bfloat16(x.y);
    __nv_bfloat16 h2 = __float2bfloat16(x.z);
    __nv_bfloat16 h3 = __float2bfloat16(x.w);
    __nv_bfloat16 l0 = __float2bfloat16(x.x - __bfloat162float(h0));
    __nv_bfloat16 l1 = __float2bfloat16(x.y - __bfloat162float(h1));
    __nv_bfloat16 l2 = __float2bfloat16(x.z - __bfloat162float(h2));
    __nv_bfloat16 l3 = __float2bfloat16(x.w - __bfloat162float(h3));
    hi[2 * i]     = __halves2bfloat162(h0, h1);
    hi[2 * i + 1] = __halves2bfloat162(h2, h3);
    lo[2 * i]     = __halves2bfloat162(l0, l1);
    lo[2 * i + 1] = __halves2bfloat162(l2, l3);
}

// ============================================================================
// W[K, N] fp32 -> Wt_hi/lo[N, K] bf16 (transpose + split); z selects matrix
// ============================================================================
__global__ void transpose_split4(const float* __restrict__ W0,
                                 const float* __restrict__ W1,
                                 const float* __restrict__ W2,
                                 const float* __restrict__ W3,
                                 __nv_bfloat16* __restrict__ h0, __nv_bfloat16* __restrict__ l0,
                                 __nv_bfloat16* __restrict__ h1, __nv_bfloat16* __restrict__ l1,
                                 __nv_bfloat16* __restrict__ h2, __nv_bfloat16* __restrict__ l2,
                                 __nv_bfloat16* __restrict__ h3, __nv_bfloat16* __restrict__ l3)
{
    const int z = blockIdx.z;
    const float* W = (z == 0) ? W0 : (z == 1) ? W1 : (z == 2) ? W2 : W3;
    __nv_bfloat16* hi = (z == 0) ? h0 : (z == 1) ? h1 : (z == 2) ? h2 : h3;
    __nv_bfloat16* lo = (z == 0) ? l0 : (z == 1) ? l1 : (z == 2) ? l2 : l3;

    __shared__ float t[32][33];
    const int kt = blockIdx.y * 32, nt = blockIdx.x * 32;
    const int tx = threadIdx.x, ty = threadIdx.y;
#pragma unroll
    for (int i = 0; i < 32; i += 8)
        t[ty + i][tx] = W[(size_t)(kt + ty + i) * D_ + nt + tx];
    __syncthreads();
#pragma unroll
    for (int i = 0; i < 32; i += 8) {
        const float x = t[tx][ty + i];
        const size_t o = (size_t)(nt + ty + i) * KDIM_ + kt + tx;
        __nv_bfloat16 h = __float2bfloat16(x);
        hi[o] = h;
        lo[o] = __float2bfloat16(x - __bfloat162float(h));
    }
}

// ============================================================================
// Tensor-core banded attention (unchanged from R6, ~100us)
// ============================================================================
#define AQHI 0
#define AQLO 16384
#define AKHI 32768
#define AKLO 49152
#define AVHI 65536
#define AVLO 81920
#define AAM  98304
#define ATT_SMEM (98304 + 256)

__device__ __forceinline__ void load64x128(uint32_t dst, const __nv_bfloat16* src, int tid)
{
#pragma unroll
    for (int v = 0; v < 8; v++) {
        const int idx = (v << 7) + tid;
        const int row = idx >> 4;
        const int c16 = idx & 15;
        CP_ASYNC16(dst + ((c16 >> 3) << 13) + SWZ(row * 128 + (c16 & 7) * 16),
                   (const char*)(src + (size_t)row * D_) + c16 * 16);
    }
}

__global__ __launch_bounds__(128)
void attn_mma(const int* __restrict__ amask)
{
    extern __shared__ __align__(1024) char sma[];
    const uint32_t sb = smem_u32(sma);
    int* am_s = (int*)(sma + AAM);

    const int tid = threadIdx.x;
    const int w   = tid >> 5;
    const int lid = tid & 31;
    const int b   = blockIdx.y >> 4;
    const int h   = blockIdx.y & 15;
    const int q0  = blockIdx.x << 6;
    const int bS  = b * S_;

    const int grp = lid >> 3, lr = lid & 7;
    const int qr  = lid >> 2;
    const int qc  = (lid & 3) << 1;

    const size_t qoff = (size_t)(bS + q0) * D_ + h * HD_;
    load64x128(sb + AQHI, g_Qhi + qoff, tid);
    load64x128(sb + AQLO, g_Qlo + qoff, tid);
    int kbeg = q0 - WINDOW_;
    if (kbeg < 0) kbeg = 0;
    const int nch = ((q0 - kbeg) >> 6) + 1;
    const size_t koff0 = (size_t)(bS + kbeg) * D_ + h * HD_;
    load64x128(sb + AKHI, g_Khi + koff0, tid);
    load64x128(sb + AKLO, g_Klo + koff0, tid);
    CP_COMMIT();
    load64x128(sb + AVHI, g_Vhi + koff0, tid);
    load64x128(sb + AVLO, g_Vlo + koff0, tid);
    CP_COMMIT();

    float m0 = -1e30f, m1 = -1e30f, l0 = 0.f, l1 = 0.f;
    float co[16][4];
#pragma unroll
    for (int i = 0; i < 16; i++)
#pragma unroll
        for (int q = 0; q < 4; q++) co[i][q] = 0.f;

    const int r0g = q0 + w * 16 + qr;
    const int r1g = r0g + 8;

    const int arow = w * 16 + (grp & 1) * 8 + lr;
    const int brow = (grp >> 1) * 8 + lr;

    for (int ci = 0; ci < nch; ci++) {
        const int k0 = kbeg + (ci << 6);
        if (tid < 64) am_s[tid] = amask[bS + k0 + tid];
        CP_WAIT1();
        __syncthreads();

        float cs[8][4];
#pragma unroll
        for (int nt = 0; nt < 8; nt++)
#pragma unroll
            for (int q = 0; q < 4; q++) cs[nt][q] = 0.f;

#pragma unroll
        for (int ks = 0; ks < 8; ks++) {
            const uint32_t ao = ((ks >> 2) << 13)
                              + SWZ(arow * 128 + (ks & 3) * 32 + (grp >> 1) * 16);
            uint32_t ah[4], al[4];
            LDSM_X4(ah, sb + AQHI + ao);
            LDSM_X4(al, sb + AQLO + ao);
            const uint32_t bw = (ks & 3) * 32 + (grp & 1) * 16;
#pragma unroll
            for (int nb = 0; nb < 4; nb++) {
                const uint32_t bo = ((ks >> 2) << 13)
                                  + SWZ((brow + nb * 16) * 128 + bw);
                uint32_t bh[4], bl[4];
                LDSM_X4(bh, sb + AKHI + bo);
                LDSM_X4(bl, sb + AKLO + bo);
                MMA_BF16(cs[2 * nb],     ah, bh[0], bh[1]);
                MMA_BF16(cs[2 * nb + 1], ah, bh[2], bh[3]);
                MMA_BF16(cs[2 * nb],     ah, bl[0], bl[1]);
                MMA_BF16(cs[2 * nb + 1], ah, bl[2], bl[3]);
                MMA_BF16(cs[2 * nb],     al, bh[0], bh[1]);
                MMA_BF16(cs[2 * nb + 1], al, bh[2], bh[3]);
            }
        }

#pragma unroll
        for (int nt = 0; nt < 8; nt++) {
            const int cl = nt * 8 + qc;
            const int c0 = k0 + cl, c1 = c0 + 1;
            const int am0 = am_s[cl], am1 = am_s[cl + 1];
            if (!(c0 <= r0g && r0g - c0 < WINDOW_ && am0)) cs[nt][0] = -1e30f;
            if (!(c1 <= r0g && r0g - c1 < WINDOW_ && am1)) cs[nt][1] = -1e30f;
            if (!(c0 <= r1g && r1g - c0 < WINDOW_ && am0)) cs[nt][2] = -1e30f;
            if (!(c1 <= r1g && r1g - c1 < WINDOW_ && am1)) cs[nt][3] = -1e30f;
        }

        float mc0 = -1e30f, mc1 = -1e30f;
#pragma unroll
        for (int nt = 0; nt < 8; nt++) {
            mc0 = fmaxf(mc0, fmaxf(cs[nt][0], cs[nt][1]));
            mc1 = fmaxf(mc1, fmaxf(cs[nt][2], cs[nt][3]));
        }
        mc0 = fmaxf(mc0, __shfl_xor_sync(0xffffffffu, mc0, 1));
        mc0 = fmaxf(mc0, __shfl_xor_sync(0xffffffffu, mc0, 2));
        mc1 = fmaxf(mc1, __shfl_xor_sync(0xffffffffu, mc1, 1));
        mc1 = fmaxf(mc1, __shfl_xor_sync(0xffffffffu, mc1, 2));
        const float mn0 = fmaxf(m0, mc0), mn1 = fmaxf(m1, mc1);
        const float sc0 = __expf(m0 - mn0), sc1 = __expf(m1 - mn1);

        float ls0 = 0.f, ls1 = 0.f;
#pragma unroll
        for (int nt = 0; nt < 8; nt++) {
            cs[nt][0] = (cs[nt][0] > -1e29f) ? __expf(cs[nt][0] - mn0) : 0.f;
            cs[nt][1] = (cs[nt][1] > -1e29f) ? __expf(cs[nt][1] - mn0) : 0.f;
            cs[nt][2] = (cs[nt][2] > -1e29f) ? __expf(cs[nt][2] - mn1) : 0.f;
            cs[nt][3] = (cs[nt][3] > -1e29f) ? __expf(cs[nt][3] - mn1) : 0.f;
            ls0 += cs[nt][0] + cs[nt][1];
            ls1 += cs[nt][2] + cs[nt][3];
        }
        ls0 += __shfl_xor_sync(0xffffffffu, ls0, 1);
        ls0 += __shfl_xor_sync(0xffffffffu, ls0, 2);
        ls1 += __shfl_xor_sync(0xffffffffu, ls1, 1);
        ls1 += __shfl_xor_sync(0xffffffffu, ls1, 2);
        l0 = l0 * sc0 + ls0;
        l1 = l1 * sc1 + ls1;
#pragma unroll
        for (int i = 0; i < 16; i++) {
            co[i][0] *= sc0; co[i][1] *= sc0;
            co[i][2] *= sc1; co[i][3] *= sc1;
        }
        m0 = mn0; m1 = mn1;

        CP_WAIT0();
        __syncthreads();
        if (ci + 1 < nch) {
            const size_t kn = (size_t)(bS + k0 + 64) * D_ + h * HD_;
            load64x128(sb + AKHI, g_Khi + kn, tid);
            load64x128(sb + AKLO, g_Klo + kn, tid);
            CP_COMMIT();
        }

#pragma unroll
        for (int ks = 0; ks < 4; ks++) {
            uint32_t phi[4], plo[4];
            phi[0] = pack_bf16(cs[2 * ks][0],     cs[2 * ks][1]);
            phi[1] = pack_bf16(cs[2 * ks][2],     cs[2 * ks][3]);
            phi[2] = pack_bf16(cs[2 * ks + 1][0], cs[2 * ks + 1][1]);
            phi[3] = pack_bf16(cs[2 * ks + 1][2], cs[2 * ks + 1][3]);
            {
                float2 f0 = unpack_bf16(phi[0]);
                float2 f1 = unpack_bf16(phi[1]);
                float2 f2 = unpack_bf16(phi[2]);
                float2 f3 = unpack_bf16(phi[3]);
                plo[0] = pack_bf16(cs[2*ks][0]   - f0.x, cs[2*ks][1]   - f0.y);
                plo[1] = pack_bf16(cs[2*ks][2]   - f1.x, cs[2*ks][3]   - f1.y);
                plo[2] = pack_bf16(cs[2*ks+1][0] - f2.x, cs[2*ks+1][1] - f2.y);
                plo[3] = pack_bf16(cs[2*ks+1][2] - f3.x, cs[2*ks+1][3] - f3.y);
            }
            const int vrow = ks * 16 + (grp & 1) * 8 + lr;
            const uint32_t vw = (grp >> 1) * 16;
#pragma unroll
            for (int g2 = 0; g2 < 8; g2++) {
                const uint32_t vo = ((g2 >> 2) << 13)
                                  + SWZ(vrow * 128 + (g2 & 3) * 32 + vw);
                uint32_t vh[4], vl[4];
                LDSM_X4_T(vh, sb + AVHI + vo);
                LDSM_X4_T(vl, sb + AVLO + vo);
                MMA_BF16(co[2 * g2],     phi, vh[0], vh[1]);
                MMA_BF16(co[2 * g2 + 1], phi, vh[2], vh[3]);
                MMA_BF16(co[2 * g2],     phi, vl[0], vl[1]);
                MMA_BF16(co[2 * g2 + 1], phi, vl[2], vl[3]);
                MMA_BF16(co[2 * g2],     plo, vh[0], vh[1]);
                MMA_BF16(co[2 * g2 + 1], plo, vh[2], vh[3]);
            }
        }
        __syncthreads();
        if (ci + 1 < nch) {
            const size_t vn = (size_t)(bS + k0 + 64) * D_ + h * HD_;
            load64x128(sb + AVHI, g_Vhi + vn, tid);
            load64x128(sb + AVLO, g_Vlo + vn, tid);
            CP_COMMIT();
        }
    }

    const float inv0 = (l0 > 0.f) ? (1.f / l0) : 0.f;
    const float inv1 = (l1 > 0.f) ? (1.f / l1) : 0.f;
    const size_t row0 = (size_t)(bS + r0g) * D_;
    const size_t row1 = (size_t)(bS + r1g) * D_;
#pragma unroll
    for (int i = 0; i < 16; i++) {
        const int col = h * HD_ + i * 8 + qc;
        const float v0 = co[i][0] * inv0, v1 = co[i][1] * inv0;
        const float v2 = co[i][2] * inv1, v3 = co[i][3] * inv1;
        uint32_t h0 = pack_bf16(v0, v1);
        uint32_t h1 = pack_bf16(v2, v3);
        float2 f0 = unpack_bf16(h0), f1 = unpack_bf16(h1);
        uint32_t l0p = pack_bf16(v0 - f0.x, v1 - f0.y);
        uint32_t l1p = pack_bf16(v2 - f1.x, v3 - f1.y);
        *(uint32_t*)(g_AOhi + row0 + col) = h0;
        *(uint32_t*)(g_AOlo + row0 + col) = l0p;
        *(uint32_t*)(g_AOhi + row1 + col) = h1;
        *(uint32_t*)(g_AOlo + row1 + col) = l1p;
    }
}

// ============================================================================
// Launch
// ============================================================================
extern "C" void kernel_launch(void* const* d_in, const int* in_sizes, int n_in,
                              void* d_out, int out_size)
{
    const float* X  = (const float*)d_in[0];
    const int*   am = (const int*)  d_in[1];
    const float* Wq = (const float*)d_in[2];
    const float* Wk = (const float*)d_in[3];
    const float* Wv = (const float*)d_in[4];
    const float* Wo = (const float*)d_in[5];
    const float* bo = (const float*)d_in[6];
    float* out = (float*)d_out;

    void *Xhi, *Xlo, *AOhi, *AOlo;
    void *Qh, *Ql, *Kh, *Kl, *Vh, *Vl;
    void *Wqh, *Wql, *Wkh, *Wkl, *Wvh, *Wvl, *Woh, *Wol;
    cudaGetSymbolAddress(&Xhi,  g_Xhi);    cudaGetSymbolAddress(&Xlo,  g_Xlo);
    cudaGetSymbolAddress(&AOhi, g_AOhi);   cudaGetSymbolAddress(&AOlo, g_AOlo);
    cudaGetSymbolAddress(&Qh,   g_Qhi);    cudaGetSymbolAddress(&Ql,   g_Qlo);
    cudaGetSymbolAddress(&Kh,   g_Khi);    cudaGetSymbolAddress(&Kl,   g_Klo);
    cudaGetSymbolAddress(&Vh,   g_Vhi);    cudaGetSymbolAddress(&Vl,   g_Vlo);
    cudaGetSymbolAddress(&Wqh,  g_Wqt_hi); cudaGetSymbolAddress(&Wql,  g_Wqt_lo);
    cudaGetSymbolAddress(&Wkh,  g_Wkt_hi); cudaGetSymbolAddress(&Wkl,  g_Wkt_lo);
    cudaGetSymbolAddress(&Wvh,  g_Wvt_hi); cudaGetSymbolAddress(&Wvl,  g_Wvt_lo);
    cudaGetSymbolAddress(&Woh,  g_Wot_hi); cudaGetSymbolAddress(&Wol,  g_Wot_lo);

    cudaFuncSetAttribute(gemm_bf16x3,
        cudaFuncAttributeMaxDynamicSharedMemorySize, GEMM_SMEM);
    cudaFuncSetAttribute(attn_mma,
        cudaFuncAttributeMaxDynamicSharedMemorySize, ATT_SMEM);

    // ---- conversions ----
    const int n4 = (MTOT_ * D_) / 4;
    split_f32x4<<<(n4 + 255) / 256, 256>>>(
        (const float4*)X, (__nv_bfloat162*)Xhi, (__nv_bfloat162*)Xlo, n4);
    transpose_split4<<<dim3(D_ / 32, D_ / 32, 4), dim3(32, 8)>>>(
        Wq, Wk, Wv, Wo,
        (__nv_bfloat16*)Wqh, (__nv_bfloat16*)Wql,
        (__nv_bfloat16*)Wkh, (__nv_bfloat16*)Wkl,
        (__nv_bfloat16*)Wvh, (__nv_bfloat16*)Wvl,
        (__nv_bfloat16*)Woh, (__nv_bfloat16*)Wol);

    // ---- merged Q/K/V GEMM (split bf16 epilogue), 256-row tiles ----
    G3 gqkv;
    gqkv.Ah  = (const __nv_bfloat16*)Xhi;  gqkv.Al  = (const __nv_bfloat16*)Xlo;
    gqkv.Bh0 = (const __nv_bfloat16*)Wqh;  gqkv.Bl0 = (const __nv_bfloat16*)Wql;
    gqkv.Bh1 = (const __nv_bfloat16*)Wkh;  gqkv.Bl1 = (const __nv_bfloat16*)Wkl;
    gqkv.Bh2 = (const __nv_bfloat16*)Wvh;  gqkv.Bl2 = (const __nv_bfloat16*)Wvl;
    gqkv.Ch0 = (__nv_bfloat16*)Qh; gqkv.Cl0 = (__nv_bfloat16*)Ql;
    gqkv.Ch1 = (__nv_bfloat16*)Kh; gqkv.Cl1 = (__nv_bfloat16*)Kl;
    gqkv.Ch2 = (__nv_bfloat16*)Vh; gqkv.Cl2 = (__nv_bfloat16*)Vl;
    gqkv.Cf = nullptr; gqkv.bias = nullptr;
    gemm_bf16x3<<<dim3(D_ / 128, MTOT_ / 256, 3), 256, GEMM_SMEM>>>(gqkv);

    // ---- tensor-core attention -> AOhi/AOlo ----
    attn_mma<<<dim3(S_ / 64, B_ * H_), 128, ATT_SMEM>>>(am);

    // ---- O GEMM (fp32 + bias) ----
    G3 go;
    go.Ah  = (const __nv_bfloat16*)AOhi; go.Al  = (const __nv_bfloat16*)AOlo;
    go.Bh0 = (const __nv_bfloat16*)Woh;  go.Bl0 = (const __nv_bfloat16*)Wol;
    go.Bh1 = go.Bh0; go.Bl1 = go.Bl0; go.Bh2 = go.Bh0; go.Bl2 = go.Bl0;
    go.Ch0 = nullptr; go.Cl0 = nullptr; go.Ch1 = nullptr; go.Cl1 = nullptr;
    go.Ch2 = nullptr; go.Cl2 = nullptr;
    go.Cf = out; go.bias = bo;
    gemm_bf16x3<<<dim3(D_ / 128, MTOT_ / 256, 1), 256, GEMM_SMEM>>>(go);
}

// round 13
// speedup vs baseline: 1.1346x; 1.1346x over previous
#include <cuda_runtime.h>
#include <cuda_bf16.h>
#include <cstdint>

#define B_ 2
#define S_ 2048
#define D_ 2048
#define H_ 16
#define HD_ 128
#define WINDOW_ 256
#define MTOT_ (B_ * S_)     // 4096
#define KDIM_ D_            // 2048

// -------- scratch (static __device__ arrays; no runtime allocation) --------
__device__ __align__(1024) __nv_bfloat16 g_Xhi [(size_t)MTOT_ * D_];
__device__ __align__(1024) __nv_bfloat16 g_Xlo [(size_t)MTOT_ * D_];
__device__ __align__(1024) __nv_bfloat16 g_Qhi [(size_t)MTOT_ * D_];
__device__ __align__(1024) __nv_bfloat16 g_Qlo [(size_t)MTOT_ * D_];
__device__ __align__(1024) __nv_bfloat16 g_Khi [(size_t)MTOT_ * D_];
__device__ __align__(1024) __nv_bfloat16 g_Klo [(size_t)MTOT_ * D_];
__device__ __align__(1024) __nv_bfloat16 g_Vhi [(size_t)MTOT_ * D_];
__device__ __align__(1024) __nv_bfloat16 g_Vlo [(size_t)MTOT_ * D_];
__device__ __align__(1024) __nv_bfloat16 g_AOhi[(size_t)MTOT_ * D_];
__device__ __align__(1024) __nv_bfloat16 g_AOlo[(size_t)MTOT_ * D_];
__device__ __align__(1024) __nv_bfloat16 g_Wqt_hi[(size_t)D_ * D_];
__device__ __align__(1024) __nv_bfloat16 g_Wqt_lo[(size_t)D_ * D_];
__device__ __align__(1024) __nv_bfloat16 g_Wkt_hi[(size_t)D_ * D_];
__device__ __align__(1024) __nv_bfloat16 g_Wkt_lo[(size_t)D_ * D_];
__device__ __align__(1024) __nv_bfloat16 g_Wvt_hi[(size_t)D_ * D_];
__device__ __align__(1024) __nv_bfloat16 g_Wvt_lo[(size_t)D_ * D_];
__device__ __align__(1024) __nv_bfloat16 g_Wot_hi[(size_t)D_ * D_];
__device__ __align__(1024) __nv_bfloat16 g_Wot_lo[(size_t)D_ * D_];

// ============================================================================
// helpers (generic PTX only — sm_80-compatible, safe for compute_103)
// ============================================================================
__device__ __forceinline__ uint32_t smem_u32(const void* p) {
    uint32_t a;
    asm("{ .reg .u64 t; cvta.to.shared.u64 t, %1; cvt.u32.u64 %0, t; }"
        : "=r"(a) : "l"(p));
    return a;
}

#define SWZ(o) ((o) ^ (((o) >> 3) & 0x70))
// packed rows: two 64B logical rows per 128B swizzled line
#define PKOFF(row, b) SWZ((((row) >> 1) << 7) + (((row) & 1) << 6) + (b))

#define CP_ASYNC16(dst, src) \
    asm volatile("cp.async.cg.shared.global [%0], [%1], 16;" \
                 :: "r"(dst), "l"(src) : "memory")
#define CP_COMMIT() asm volatile("cp.async.commit_group;" ::: "memory")
#define CP_WAIT0()  asm volatile("cp.async.wait_group 0;" ::: "memory")
#define CP_WAIT1()  asm volatile("cp.async.wait_group 1;" ::: "memory")

#define LDSM_X4(rr, addr) \
    asm volatile("ldmatrix.sync.aligned.m8n8.x4.shared.b16 {%0,%1,%2,%3}, [%4];" \
        : "=r"((rr)[0]), "=r"((rr)[1]), "=r"((rr)[2]), "=r"((rr)[3]) : "r"(addr))

#define LDSM_X4_T(rr, addr) \
    asm volatile("ldmatrix.sync.aligned.m8n8.x4.trans.shared.b16 {%0,%1,%2,%3}, [%4];" \
        : "=r"((rr)[0]), "=r"((rr)[1]), "=r"((rr)[2]), "=r"((rr)[3]) : "r"(addr))

#define MMA_BF16(cc, aa, b0, b1) \
    asm volatile("mma.sync.aligned.m16n8k16.row.col.f32.bf16.bf16.f32 " \
        "{%0,%1,%2,%3}, {%4,%5,%6,%7}, {%8,%9}, {%0,%1,%2,%3};" \
        : "+f"((cc)[0]), "+f"((cc)[1]), "+f"((cc)[2]), "+f"((cc)[3]) \
        : "r"((aa)[0]), "r"((aa)[1]), "r"((aa)[2]), "r"((aa)[3]), \
          "r"(b0), "r"(b1))

// pack two f32 into bf16x2: low half = lo, high half = hi
__device__ __forceinline__ uint32_t pack_bf16(float lo, float hi) {
    uint32_t r;
    asm("cvt.rn.bf16x2.f32 %0, %1, %2;" : "=r"(r) : "f"(hi), "f"(lo));
    return r;
}
__device__ __forceinline__ float2 unpack_bf16(uint32_t u) {
    __nv_bfloat162 b = *reinterpret_cast<__nv_bfloat162*>(&u);
    return make_float2(__bfloat162float(b.x), __bfloat162float(b.y));
}

// ============================================================================
// bf16 3-split GEMM via mma.sync: 128x128 CTA tile, 4 warps (64x64 each),
// BK=32 packed-row layout, 3-stage cp.async pipeline, 2 CTAs/SM.
// D = Ah*Bh + Ah*Bl + Al*Bh (fp32 accum).
// R13: pass-major MMA order — each accumulator touched once per nb-sweep
// (reuse distance 8 MMAs > HMMA latency) to break RAW stalls.
// ============================================================================
#define TILE_B2 8192       // one 128x32 bf16 tile (packed rows)
#define STAGE_B 32768      // Ah|Al|Bh|Bl
#define NCHUNKS 64         // K / 32
#define GEMM_SMEM (3 * STAGE_B)   // 98304 -> 2 CTAs/SM

struct G3 {
    const __nv_bfloat16 *Ah, *Al;
    const __nv_bfloat16 *Bh0, *Bl0, *Bh1, *Bl1, *Bh2, *Bl2;
    __nv_bfloat16 *Ch0, *Cl0, *Ch1, *Cl1, *Ch2, *Cl2;   // split outputs
    float* Cf;                                           // fp32 output
    const float* bias;
};

__device__ __forceinline__ void issue_chunk(
    const __nv_bfloat16* Ah, const __nv_bfloat16* Al,
    const __nv_bfloat16* Bh, const __nv_bfloat16* Bl,
    int t, int tid, int m0, int n0, uint32_t sb)
{
    const int k0 = t << 5;   // BK = 32
    const uint32_t stg = sb + (t % 3) * STAGE_B;
#pragma unroll
    for (int v = 0; v < 16; v++) {
        const int tile = v >> 2;               // 0=Ah 1=Al 2=Bh 3=Bl
        const int slot = ((v & 3) << 7) + tid; // 0..511
        const int row  = slot >> 2;            // 0..127
        const int c16  = slot & 3;             // 0..3 (16B within 64B row)
        const uint32_t dst = stg + (tile << 13) + PKOFF(row, c16 * 16);
        const __nv_bfloat16* base =
            (tile == 0) ? Ah : (tile == 1) ? Al : (tile == 2) ? Bh : Bl;
        const int r0 = (tile < 2) ? m0 : n0;
        CP_ASYNC16(dst, (const char*)(base + (size_t)(r0 + row) * KDIM_ + k0)
                        + c16 * 16);
    }
}

__global__ __launch_bounds__(128, 2)
void gemm_bf16x3(G3 ga)
{
    extern __shared__ __align__(1024) char smg[];
    const uint32_t sb = smem_u32(smg);
    const int tid = threadIdx.x;
    const int wid = tid >> 5, lid = tid & 31;
    const int warp_m = wid & 1;        // 0..1 (64 rows)
    const int warp_n = wid >> 1;       // 0..1 (64 cols)
    const int m0 = blockIdx.y << 7;
    const int n0 = blockIdx.x << 7;
    const int z  = blockIdx.z;

    const __nv_bfloat16* Bh = (z == 0) ? ga.Bh0 : (z == 1) ? ga.Bh1 : ga.Bh2;
    const __nv_bfloat16* Bl = (z == 0) ? ga.Bl0 : (z == 1) ? ga.Bl1 : ga.Bl2;

    const int grp = lid >> 3;
    const int lr  = lid & 7;

    float c[4][8][4];
#pragma unroll
    for (int mt = 0; mt < 4; mt++)
#pragma unroll
        for (int nt = 0; nt < 8; nt++)
#pragma unroll
            for (int q = 0; q < 4; q++) c[mt][nt][q] = 0.f;

    const int a_row = warp_m * 64 + (grp & 1) * 8 + lr;   // + mt*16
    const int a_kb  = (grp >> 1) * 16;                    // + kt*32
    const int b_row = warp_n * 64 + (grp >> 1) * 8 + lr;  // + nb*16
    const int b_kb  = (grp & 1) * 16;                     // + kt*32

    issue_chunk(ga.Ah, ga.Al, Bh, Bl, 0, tid, m0, n0, sb); CP_COMMIT();
    issue_chunk(ga.Ah, ga.Al, Bh, Bl, 1, tid, m0, n0, sb); CP_COMMIT();

    for (int t = 0; t < NCHUNKS; t++) {
        CP_WAIT1();
        __syncthreads();
        if (t + 2 < NCHUNKS)
            issue_chunk(ga.Ah, ga.Al, Bh, Bl, t + 2, tid, m0, n0, sb);
        CP_COMMIT();

        const uint32_t Ahs = sb + (t % 3) * STAGE_B;
        const uint32_t Als = Ahs + TILE_B2;
        const uint32_t Bhs = Ahs + 2 * TILE_B2;
        const uint32_t Bls = Ahs + 3 * TILE_B2;

#pragma unroll
        for (int kt = 0; kt < 2; kt++) {
            uint32_t bh[4][4], bl[4][4];
#pragma unroll
            for (int nb = 0; nb < 4; nb++) {
                const uint32_t bo = PKOFF(b_row + nb * 16, kt * 32 + b_kb);
                LDSM_X4(bh[nb], Bhs + bo);
                LDSM_X4(bl[nb], Bls + bo);
            }
#pragma unroll
            for (int mt = 0; mt < 4; mt++) {
                uint32_t ah[4], al[4];
                const uint32_t ao = PKOFF(a_row + mt * 16, kt * 32 + a_kb);
                LDSM_X4(ah, Ahs + ao);
                LDSM_X4(al, Als + ao);
                // pass-major: accumulator reuse distance = 8 MMAs
#pragma unroll
                for (int nb = 0; nb < 4; nb++) {
                    MMA_BF16(c[mt][2 * nb],     ah, bh[nb][0], bh[nb][1]);
                    MMA_BF16(c[mt][2 * nb + 1], ah, bh[nb][2], bh[nb][3]);
                }
#pragma unroll
                for (int nb = 0; nb < 4; nb++) {
                    MMA_BF16(c[mt][2 * nb],     ah, bl[nb][0], bl[nb][1]);
                    MMA_BF16(c[mt][2 * nb + 1], ah, bl[nb][2], bl[nb][3]);
                }
#pragma unroll
                for (int nb = 0; nb < 4; nb++) {
                    MMA_BF16(c[mt][2 * nb],     al, bh[nb][0], bh[nb][1]);
                    MMA_BF16(c[mt][2 * nb + 1], al, bh[nb][2], bh[nb][3]);
                }
            }
        }
        __syncthreads();
    }

    // ---- epilogue ----
    const int l4 = lid >> 2;
    const int l2 = (lid & 3) << 1;
    if (ga.Cf) {
        float* C = ga.Cf;
#pragma unroll
        for (int mt = 0; mt < 4; mt++) {
            const int row = m0 + warp_m * 64 + mt * 16 + l4;
#pragma unroll
            for (int nt = 0; nt < 8; nt++) {
                const int col = n0 + warp_n * 64 + nt * 8 + l2;
                float2 v0 = make_float2(c[mt][nt][0], c[mt][nt][1]);
                float2 v1 = make_float2(c[mt][nt][2], c[mt][nt][3]);
                const float b0 = ga.bias[col], b1 = ga.bias[col + 1];
                v0.x += b0; v0.y += b1;
                v1.x += b0; v1.y += b1;
                *(float2*)(C + (size_t)row * D_ + col)       = v0;
                *(float2*)(C + (size_t)(row + 8) * D_ + col) = v1;
            }
        }
    } else {
        __nv_bfloat16* Ch = (z == 0) ? ga.Ch0 : (z == 1) ? ga.Ch1 : ga.Ch2;
        __nv_bfloat16* Cl = (z == 0) ? ga.Cl0 : (z == 1) ? ga.Cl1 : ga.Cl2;
#pragma unroll
        for (int mt = 0; mt < 4; mt++) {
            const int row = m0 + warp_m * 64 + mt * 16 + l4;
#pragma unroll
            for (int nt = 0; nt < 8; nt++) {
                const int col = n0 + warp_n * 64 + nt * 8 + l2;
                const size_t o0 = (size_t)row * D_ + col;
                const size_t o1 = (size_t)(row + 8) * D_ + col;
                uint32_t h0 = pack_bf16(c[mt][nt][0], c[mt][nt][1]);
                uint32_t h1 = pack_bf16(c[mt][nt][2], c[mt][nt][3]);
                float2 f0 = unpack_bf16(h0), f1 = unpack_bf16(h1);
                uint32_t l0p = pack_bf16(c[mt][nt][0] - f0.x, c[mt][nt][1] - f0.y);
                uint32_t l1p = pack_bf16(c[mt][nt][2] - f1.x, c[mt][nt][3] - f1.y);
                *(uint32_t*)(Ch + o0) = h0;
                *(uint32_t*)(Ch + o1) = h1;
                *(uint32_t*)(Cl + o0) = l0p;
                *(uint32_t*)(Cl + o1) = l1p;
            }
        }
    }
}

// ============================================================================
// fp32 -> (hi, lo) bf16 split, elementwise (vectorized x4)
// ============================================================================
__global__ void split_f32x4(const float4* __restrict__ in,
                            __nv_bfloat162* __restrict__ hi,
                            __nv_bfloat162* __restrict__ lo, int n4)
{
    int i = blockIdx.x * blockDim.x + threadIdx.x;
    if (i >= n4) return;
    float4 x = in[i];
    __nv_bfloat16 h0 = __float2bfloat16(x.x);
    __nv_bfloat16 h1 = __float2bfloat16(x.y);
    __nv_bfloat16 h2 = __float2bfloat16(x.z);
    __nv_bfloat16 h3 = __float2bfloat16(x.w);
    __nv_bfloat16 l0 = __float2bfloat16(x.x - __bfloat162float(h0));
    __nv_bfloat16 l1 = __float2bfloat16(x.y - __bfloat162float(h1));
    __nv_bfloat16 l2 = __float2bfloat16(x.z - __bfloat162float(h2));
    __nv_bfloat16 l3 = __float2bfloat16(x.w - __bfloat162float(h3));
    hi[2 * i]     = __halves2bfloat162(h0, h1);
    hi[2 * i + 1] = __halves2bfloat162(h2, h3);
    lo[2 * i]     = __halves2bfloat162(l0, l1);
    lo[2 * i + 1] = __halves2bfloat162(l2, l3);
}

// ============================================================================
// W[K, N] fp32 -> Wt_hi/lo[N, K] bf16 (transpose + split); z selects matrix
// ============================================================================
__global__ void transpose_split4(const float* __restrict__ W0,
                                 const float* __restrict__ W1,
                                 const float* __restrict__ W2,
                                 const float* __restrict__ W3,
                                 __nv_bfloat16* __restrict__ h0, __nv_bfloat16* __restrict__ l0,
                                 __nv_bfloat16* __restrict__ h1, __nv_bfloat16* __restrict__ l1,
                                 __nv_bfloat16* __restrict__ h2, __nv_bfloat16* __restrict__ l2,
                                 __nv_bfloat16* __restrict__ h3, __nv_bfloat16* __restrict__ l3)
{
    const int z = blockIdx.z;
    const float* W = (z == 0) ? W0 : (z == 1) ? W1 : (z == 2) ? W2 : W3;
    __nv_bfloat16* hi = (z == 0) ? h0 : (z == 1) ? h1 : (z == 2) ? h2 : h3;
    __nv_bfloat16* lo = (z == 0) ? l0 : (z == 1) ? l1 : (z == 2) ? l2 : l3;

    __shared__ float t[32][33];
    const int kt = blockIdx.y * 32, nt = blockIdx.x * 32;
    const int tx = threadIdx.x, ty = threadIdx.y;
#pragma unroll
    for (int i = 0; i < 32; i += 8)
        t[ty + i][tx] = W[(size_t)(kt + ty + i) * D_ + nt + tx];
    __syncthreads();
#pragma unroll
    for (int i = 0; i < 32; i += 8) {
        const float x = t[tx][ty + i];
        const size_t o = (size_t)(nt + ty + i) * KDIM_ + kt + tx;
        __nv_bfloat16 h = __float2bfloat16(x);
        hi[o] = h;
        lo[o] = __float2bfloat16(x - __bfloat162float(h));
    }
}

// ============================================================================
// Tensor-core banded attention (unchanged from R6, ~100us)
// ============================================================================
#define AQHI 0
#define AQLO 16384
#define AKHI 32768
#define AKLO 49152
#define AVHI 65536
#define AVLO 81920
#define AAM  98304
#define ATT_SMEM (98304 + 256)

__device__ __forceinline__ void load64x128(uint32_t dst, const __nv_bfloat16* src, int tid)
{
#pragma unroll
    for (int v = 0; v < 8; v++) {
        const int idx = (v << 7) + tid;
        const int row = idx >> 4;
        const int c16 = idx & 15;
        CP_ASYNC16(dst + ((c16 >> 3) << 13) + SWZ(row * 128 + (c16 & 7) * 16),
                   (const char*)(src + (size_t)row * D_) + c16 * 16);
    }
}

__global__ __launch_bounds__(128)
void attn_mma(const int* __restrict__ amask)
{
    extern __shared__ __align__(1024) char sma[];
    const uint32_t sb = smem_u32(sma);
    int* am_s = (int*)(sma + AAM);

    const int tid = threadIdx.x;
    const int w   = tid >> 5;
    const int lid = tid & 31;
    const int b   = blockIdx.y >> 4;
    const int h   = blockIdx.y & 15;
    const int q0  = blockIdx.x << 6;
    const int bS  = b * S_;

    const int grp = lid >> 3, lr = lid & 7;
    const int qr  = lid >> 2;
    const int qc  = (lid & 3) << 1;

    const size_t qoff = (size_t)(bS + q0) * D_ + h * HD_;
    load64x128(sb + AQHI, g_Qhi + qoff, tid);
    load64x128(sb + AQLO, g_Qlo + qoff, tid);
    int kbeg = q0 - WINDOW_;
    if (kbeg < 0) kbeg = 0;
    const int nch = ((q0 - kbeg) >> 6) + 1;
    const size_t koff0 = (size_t)(bS + kbeg) * D_ + h * HD_;
    load64x128(sb + AKHI, g_Khi + koff0, tid);
    load64x128(sb + AKLO, g_Klo + koff0, tid);
    CP_COMMIT();
    load64x128(sb + AVHI, g_Vhi + koff0, tid);
    load64x128(sb + AVLO, g_Vlo + koff0, tid);
    CP_COMMIT();

    float m0 = -1e30f, m1 = -1e30f, l0 = 0.f, l1 = 0.f;
    float co[16][4];
#pragma unroll
    for (int i = 0; i < 16; i++)
#pragma unroll
        for (int q = 0; q < 4; q++) co[i][q] = 0.f;

    const int r0g = q0 + w * 16 + qr;
    const int r1g = r0g + 8;

    const int arow = w * 16 + (grp & 1) * 8 + lr;
    const int brow = (grp >> 1) * 8 + lr;

    for (int ci = 0; ci < nch; ci++) {
        const int k0 = kbeg + (ci << 6);
        if (tid < 64) am_s[tid] = amask[bS + k0 + tid];
        CP_WAIT1();
        __syncthreads();

        float cs[8][4];
#pragma unroll
        for (int nt = 0; nt < 8; nt++)
#pragma unroll
            for (int q = 0; q < 4; q++) cs[nt][q] = 0.f;

#pragma unroll
        for (int ks = 0; ks < 8; ks++) {
            const uint32_t ao = ((ks >> 2) << 13)
                              + SWZ(arow * 128 + (ks & 3) * 32 + (grp >> 1) * 16);
            uint32_t ah[4], al[4];
            LDSM_X4(ah, sb + AQHI + ao);
            LDSM_X4(al, sb + AQLO + ao);
            const uint32_t bw = (ks & 3) * 32 + (grp & 1) * 16;
#pragma unroll
            for (int nb = 0; nb < 4; nb++) {
                const uint32_t bo = ((ks >> 2) << 13)
                                  + SWZ((brow + nb * 16) * 128 + bw);
                uint32_t bh[4], bl[4];
                LDSM_X4(bh, sb + AKHI + bo);
                LDSM_X4(bl, sb + AKLO + bo);
                MMA_BF16(cs[2 * nb],     ah, bh[0], bh[1]);
                MMA_BF16(cs[2 * nb + 1], ah, bh[2], bh[3]);
                MMA_BF16(cs[2 * nb],     ah, bl[0], bl[1]);
                MMA_BF16(cs[2 * nb + 1], ah, bl[2], bl[3]);
                MMA_BF16(cs[2 * nb],     al, bh[0], bh[1]);
                MMA_BF16(cs[2 * nb + 1], al, bh[2], bh[3]);
            }
        }

#pragma unroll
        for (int nt = 0; nt < 8; nt++) {
            const int cl = nt * 8 + qc;
            const int c0 = k0 + cl, c1 = c0 + 1;
            const int am0 = am_s[cl], am1 = am_s[cl + 1];
            if (!(c0 <= r0g && r0g - c0 < WINDOW_ && am0)) cs[nt][0] = -1e30f;
            if (!(c1 <= r0g && r0g - c1 < WINDOW_ && am1)) cs[nt][1] = -1e30f;
            if (!(c0 <= r1g && r1g - c0 < WINDOW_ && am0)) cs[nt][2] = -1e30f;
            if (!(c1 <= r1g && r1g - c1 < WINDOW_ && am1)) cs[nt][3] = -1e30f;
        }

        float mc0 = -1e30f, mc1 = -1e30f;
#pragma unroll
        for (int nt = 0; nt < 8; nt++) {
            mc0 = fmaxf(mc0, fmaxf(cs[nt][0], cs[nt][1]));
            mc1 = fmaxf(mc1, fmaxf(cs[nt][2], cs[nt][3]));
        }
        mc0 = fmaxf(mc0, __shfl_xor_sync(0xffffffffu, mc0, 1));
        mc0 = fmaxf(mc0, __shfl_xor_sync(0xffffffffu, mc0, 2));
        mc1 = fmaxf(mc1, __shfl_xor_sync(0xffffffffu, mc1, 1));
        mc1 = fmaxf(mc1, __shfl_xor_sync(0xffffffffu, mc1, 2));
        const float mn0 = fmaxf(m0, mc0), mn1 = fmaxf(m1, mc1);
        const float sc0 = __expf(m0 - mn0), sc1 = __expf(m1 - mn1);

        float ls0 = 0.f, ls1 = 0.f;
#pragma unroll
        for (int nt = 0; nt < 8; nt++) {
            cs[nt][0] = (cs[nt][0] > -1e29f) ? __expf(cs[nt][0] - mn0) : 0.f;
            cs[nt][1] = (cs[nt][1] > -1e29f) ? __expf(cs[nt][1] - mn0) : 0.f;
            cs[nt][2] = (cs[nt][2] > -1e29f) ? __expf(cs[nt][2] - mn1) : 0.f;
            cs[nt][3] = (cs[nt][3] > -1e29f) ? __expf(cs[nt][3] - mn1) : 0.f;
            ls0 += cs[nt][0] + cs[nt][1];
            ls1 += cs[nt][2] + cs[nt][3];
        }
        ls0 += __shfl_xor_sync(0xffffffffu, ls0, 1);
        ls0 += __shfl_xor_sync(0xffffffffu, ls0, 2);
        ls1 += __shfl_xor_sync(0xffffffffu, ls1, 1);
        ls1 += __shfl_xor_sync(0xffffffffu, ls1, 2);
        l0 = l0 * sc0 + ls0;
        l1 = l1 * sc1 + ls1;
#pragma unroll
        for (int i = 0; i < 16; i++) {
            co[i][0] *= sc0; co[i][1] *= sc0;
            co[i][2] *= sc1; co[i][3] *= sc1;
        }
        m0 = mn0; m1 = mn1;

        CP_WAIT0();
        __syncthreads();
        if (ci + 1 < nch) {
            const size_t kn = (size_t)(bS + k0 + 64) * D_ + h * HD_;
            load64x128(sb + AKHI, g_Khi + kn, tid);
            load64x128(sb + AKLO, g_Klo + kn, tid);
            CP_COMMIT();
        }

#pragma unroll
        for (int ks = 0; ks < 4; ks++) {
            uint32_t phi[4], plo[4];
            phi[0] = pack_bf16(cs[2 * ks][0],     cs[2 * ks][1]);
            phi[1] = pack_bf16(cs[2 * ks][2],     cs[2 * ks][3]);
            phi[2] = pack_bf16(cs[2 * ks + 1][0], cs[2 * ks + 1][1]);
            phi[3] = pack_bf16(cs[2 * ks + 1][2], cs[2 * ks + 1][3]);
            {
                float2 f0 = unpack_bf16(phi[0]);
                float2 f1 = unpack_bf16(phi[1]);
                float2 f2 = unpack_bf16(phi[2]);
                float2 f3 = unpack_bf16(phi[3]);
                plo[0] = pack_bf16(cs[2*ks][0]   - f0.x, cs[2*ks][1]   - f0.y);
                plo[1] = pack_bf16(cs[2*ks][2]   - f1.x, cs[2*ks][3]   - f1.y);
                plo[2] = pack_bf16(cs[2*ks+1][0] - f2.x, cs[2*ks+1][1] - f2.y);
                plo[3] = pack_bf16(cs[2*ks+1][2] - f3.x, cs[2*ks+1][3] - f3.y);
            }
            const int vrow = ks * 16 + (grp & 1) * 8 + lr;
            const uint32_t vw = (grp >> 1) * 16;
#pragma unroll
            for (int g2 = 0; g2 < 8; g2++) {
                const uint32_t vo = ((g2 >> 2) << 13)
                                  + SWZ(vrow * 128 + (g2 & 3) * 32 + vw);
                uint32_t vh[4], vl[4];
                LDSM_X4_T(vh, sb + AVHI + vo);
                LDSM_X4_T(vl, sb + AVLO + vo);
                MMA_BF16(co[2 * g2],     phi, vh[0], vh[1]);
                MMA_BF16(co[2 * g2 + 1], phi, vh[2], vh[3]);
                MMA_BF16(co[2 * g2],     phi, vl[0], vl[1]);
                MMA_BF16(co[2 * g2 + 1], phi, vl[2], vl[3]);
                MMA_BF16(co[2 * g2],     plo, vh[0], vh[1]);
                MMA_BF16(co[2 * g2 + 1], plo, vh[2], vh[3]);
            }
        }
        __syncthreads();
        if (ci + 1 < nch) {
            const size_t vn = (size_t)(bS + k0 + 64) * D_ + h * HD_;
            load64x128(sb + AVHI, g_Vhi + vn, tid);
            load64x128(sb + AVLO, g_Vlo + vn, tid);
            CP_COMMIT();
        }
    }

    const float inv0 = (l0 > 0.f) ? (1.f / l0) : 0.f;
    const float inv1 = (l1 > 0.f) ? (1.f / l1) : 0.f;
    const size_t row0 = (size_t)(bS + r0g) * D_;
    const size_t row1 = (size_t)(bS + r1g) * D_;
#pragma unroll
    for (int i = 0; i < 16; i++) {
        const int col = h * HD_ + i * 8 + qc;
        const float v0 = co[i][0] * inv0, v1 = co[i][1] * inv0;
        const float v2 = co[i][2] * inv1, v3 = co[i][3] * inv1;
        uint32_t h0 = pack_bf16(v0, v1);
        uint32_t h1 = pack_bf16(v2, v3);
        float2 f0 = unpack_bf16(h0), f1 = unpack_bf16(h1);
        uint32_t l0p = pack_bf16(v0 - f0.x, v1 - f0.y);
        uint32_t l1p = pack_bf16(v2 - f1.x, v3 - f1.y);
        *(uint32_t*)(g_AOhi + row0 + col) = h0;
        *(uint32_t*)(g_AOlo + row0 + col) = l0p;
        *(uint32_t*)(g_AOhi + row1 + col) = h1;
        *(uint32_t*)(g_AOlo + row1 + col) = l1p;
    }
}

// ============================================================================
// Launch
// ============================================================================
extern "C" void kernel_launch(void* const* d_in, const int* in_sizes, int n_in,
                              void* d_out, int out_size)
{
    const float* X  = (const float*)d_in[0];
    const int*   am = (const int*)  d_in[1];
    const float* Wq = (const float*)d_in[2];
    const float* Wk = (const float*)d_in[3];
    const float* Wv = (const float*)d_in[4];
    const float* Wo = (const float*)d_in[5];
    const float* bo = (const float*)d_in[6];
    float* out = (float*)d_out;

    void *Xhi, *Xlo, *AOhi, *AOlo;
    void *Qh, *Ql, *Kh, *Kl, *Vh, *Vl;
    void *Wqh, *Wql, *Wkh, *Wkl, *Wvh, *Wvl, *Woh, *Wol;
    cudaGetSymbolAddress(&Xhi,  g_Xhi);    cudaGetSymbolAddress(&Xlo,  g_Xlo);
    cudaGetSymbolAddress(&AOhi, g_AOhi);   cudaGetSymbolAddress(&AOlo, g_AOlo);
    cudaGetSymbolAddress(&Qh,   g_Qhi);    cudaGetSymbolAddress(&Ql,   g_Qlo);
    cudaGetSymbolAddress(&Kh,   g_Khi);    cudaGetSymbolAddress(&Kl,   g_Klo);
    cudaGetSymbolAddress(&Vh,   g_Vhi);    cudaGetSymbolAddress(&Vl,   g_Vlo);
    cudaGetSymbolAddress(&Wqh,  g_Wqt_hi); cudaGetSymbolAddress(&Wql,  g_Wqt_lo);
    cudaGetSymbolAddress(&Wkh,  g_Wkt_hi); cudaGetSymbolAddress(&Wkl,  g_Wkt_lo);
    cudaGetSymbolAddress(&Wvh,  g_Wvt_hi); cudaGetSymbolAddress(&Wvl,  g_Wvt_lo);
    cudaGetSymbolAddress(&Woh,  g_Wot_hi); cudaGetSymbolAddress(&Wol,  g_Wot_lo);

    cudaFuncSetAttribute(gemm_bf16x3,
        cudaFuncAttributeMaxDynamicSharedMemorySize, GEMM_SMEM);
    cudaFuncSetAttribute(attn_mma,
        cudaFuncAttributeMaxDynamicSharedMemorySize, ATT_SMEM);

    // ---- conversions ----
    const int n4 = (MTOT_ * D_) / 4;
    split_f32x4<<<(n4 + 255) / 256, 256>>>(
        (const float4*)X, (__nv_bfloat162*)Xhi, (__nv_bfloat162*)Xlo, n4);
    transpose_split4<<<dim3(D_ / 32, D_ / 32, 4), dim3(32, 8)>>>(
        Wq, Wk, Wv, Wo,
        (__nv_bfloat16*)Wqh, (__nv_bfloat16*)Wql,
        (__nv_bfloat16*)Wkh, (__nv_bfloat16*)Wkl,
        (__nv_bfloat16*)Wvh, (__nv_bfloat16*)Wvl,
        (__nv_bfloat16*)Woh, (__nv_bfloat16*)Wol);

    // ---- merged Q/K/V GEMM (split bf16 epilogue) ----
    G3 gqkv;
    gqkv.Ah  = (const __nv_bfloat16*)Xhi;  gqkv.Al  = (const __nv_bfloat16*)Xlo;
    gqkv.Bh0 = (const __nv_bfloat16*)Wqh;  gqkv.Bl0 = (const __nv_bfloat16*)Wql;
    gqkv.Bh1 = (const __nv_bfloat16*)Wkh;  gqkv.Bl1 = (const __nv_bfloat16*)Wkl;
    gqkv.Bh2 = (const __nv_bfloat16*)Wvh;  gqkv.Bl2 = (const __nv_bfloat16*)Wvl;
    gqkv.Ch0 = (__nv_bfloat16*)Qh; gqkv.Cl0 = (__nv_bfloat16*)Ql;
    gqkv.Ch1 = (__nv_bfloat16*)Kh; gqkv.Cl1 = (__nv_bfloat16*)Kl;
    gqkv.Ch2 = (__nv_bfloat16*)Vh; gqkv.Cl2 = (__nv_bfloat16*)Vl;
    gqkv.Cf = nullptr; gqkv.bias = nullptr;
    gemm_bf16x3<<<dim3(D_ / 128, MTOT_ / 128, 3), 128, GEMM_SMEM>>>(gqkv);

    // ---- tensor-core attention -> AOhi/AOlo ----
    attn_mma<<<dim3(S_ / 64, B_ * H_), 128, ATT_SMEM>>>(am);

    // ---- O GEMM (fp32 + bias) ----
    G3 go;
    go.Ah  = (const __nv_bfloat16*)AOhi; go.Al  = (const __nv_bfloat16*)AOlo;
    go.Bh0 = (const __nv_bfloat16*)Woh;  go.Bl0 = (const __nv_bfloat16*)Wol;
    go.Bh1 = go.Bh0; go.Bl1 = go.Bl0; go.Bh2 = go.Bh0; go.Bl2 = go.Bl0;
    go.Ch0 = nullptr; go.Cl0 = nullptr; go.Ch1 = nullptr; go.Cl1 = nullptr;
    go.Ch2 = nullptr; go.Cl2 = nullptr;
    go.Cf = out; go.bias = bo;
    gemm_bf16x3<<<dim3(D_ / 128, MTOT_ / 128, 1), 128, GEMM_SMEM>>>(go);
}